// round 1
// baseline (speedup 1.0000x reference)
#include <cuda_runtime.h>
#include <cstdint>

// Problem constants
#define Bc      32
#define Lc      32768
#define Mc      32
#define Dc      128
#define Kc      16
#define STRIDEc 8
#define Pc      4095          // (L - K)/STRIDE + 1
#define RED     512           // M*K reduction length
#define TILE_P  32
#define XROWS   (TILE_P * STRIDEc + (Kc - STRIDEc))   // 264 rows of x per block
#define XELEMS  (XROWS * Mc)                          // 8448 floats (= 33*256)

// Transposed weights: g_Wt[kk*128 + d] = conv_w[d][m][k], kk = k*32 + m.
// This matches the contiguous layout of the x window: x[b, p*8+k, m] is at
// offset p*256 + kk within the block's x tile.
__device__ float g_Wt[RED * Dc];

__global__ void wt_transpose_kernel(const float* __restrict__ w) {
    int idx = blockIdx.x * blockDim.x + threadIdx.x;   // 0..65535
    if (idx >= RED * Dc) return;
    int kk = idx >> 7;        // 0..511
    int d  = idx & 127;
    int k  = kk >> 5;
    int m  = kk & 31;
    g_Wt[idx] = w[d * (Mc * Kc) + m * Kc + k];
}

__global__ __launch_bounds__(256) void patch_encoder_kernel(
    const float* __restrict__ x,
    const float* __restrict__ ts,
    const float* __restrict__ cb,
    float* __restrict__ out)
{
    // x tile: 264 rows x 32 channels, contiguous slab of global x
    __shared__ float xs[XELEMS];                       // 33792 B
    // W chunk, pair-swizzled: ws2[g][mm][td] holds the packed float pair
    //   g=0 -> (d=4*td+0, d=4*td+1), g=1 -> (d=4*td+2, d=4*td+3)
    // so each lane's 8-byte read is lane-contiguous (conflict-free).
    __shared__ unsigned long long ws2[2][16][32];      // 8192 B

    const int b   = blockIdx.y;
    const int p0  = blockIdx.x * TILE_P;
    const int tid = threadIdx.x;
    const int td  = tid & 31;     // d-tile: d = 4*td + {0..3}
    const int tp  = tid >> 5;     // p-tile: p = p0 + 4*tp + {0..3}

    // ---- stage x tile (coalesced; zero-fill past end of L for last block) ----
    const float* xb = x + ((size_t)b * Lc + (size_t)p0 * STRIDEc) * Mc;
    const int avail = (Lc - p0 * STRIDEc) * Mc;        // elements available in x
    #pragma unroll
    for (int it = 0; it < XELEMS / 256; ++it) {
        int e = it * 256 + tid;
        xs[e] = (e < avail) ? xb[e] : 0.0f;
    }

    // 8 packed f32x2 accumulators: acc[i][jp] = (d_low, d_high) pair for p-index i
    unsigned long long acc[4][2];
    #pragma unroll
    for (int i = 0; i < 4; ++i) { acc[i][0] = 0ull; acc[i][1] = 0ull; }

    float* wsf = (float*)ws2;

    // ---- main reduction: 32 chunks of 16 kk each ----
    for (int c = 0; c < 32; ++c) {
        __syncthreads();
        // stage W chunk [c*16 .. c*16+16) x 128d into swizzled smem
        #pragma unroll
        for (int it = 0; it < 8; ++it) {
            int e  = it * 256 + tid;          // 0..2047
            int mm = e >> 7;                  // kk within chunk
            int d  = e & 127;
            float v = g_Wt[c * 2048 + e];
            int g   = (d >> 1) & 1;
            int tdw = d >> 2;
            wsf[((g * 16 + mm) * 32 + tdw) * 2 + (d & 1)] = v;
        }
        __syncthreads();

        #pragma unroll
        for (int mm = 0; mm < 16; ++mm) {
            const int kk = c * 16 + mm;
            const unsigned long long w01 = ws2[0][mm][td];
            const unsigned long long w23 = ws2[1][mm][td];
            #pragma unroll
            for (int i = 0; i < 4; ++i) {
                float xv = xs[(tp * 4 + i) * 256 + kk];   // warp-uniform -> broadcast
                unsigned long long xp;
                asm("mov.b64 %0, {%1, %1};" : "=l"(xp) : "r"(__float_as_uint(xv)));
                asm("fma.rn.f32x2 %0, %1, %2, %0;" : "+l"(acc[i][0]) : "l"(xp), "l"(w01));
                asm("fma.rn.f32x2 %0, %1, %2, %0;" : "+l"(acc[i][1]) : "l"(xp), "l"(w23));
            }
        }
    }

    // ---- epilogue: bias + sinusoidal PE (median == ts[p*8+7], window pre-sorted) ----
    const float C = -0.07195578f;            // -ln(10000)/128
    const float dt0 = __expf((float)(4 * td)     * C) * 0.0f + expf((float)(4 * td)     * C);
    const float dt1 = expf((float)(4 * td + 2) * C);
    const float4 cb4 = ((const float4*)cb)[td];

    #pragma unroll
    for (int i = 0; i < 4; ++i) {
        int p = p0 + tp * 4 + i;
        if (p >= Pc) continue;
        float med = ts[(size_t)b * Lc + p * STRIDEc + 7];
        float s0, c0, s1, c1;
        sincosf(med * dt0, &s0, &c0);
        sincosf(med * dt1, &s1, &c1);

        unsigned int a0, a1, a2, a3;
        asm("mov.b64 {%0, %1}, %2;" : "=r"(a0), "=r"(a1) : "l"(acc[i][0]));
        asm("mov.b64 {%0, %1}, %2;" : "=r"(a2), "=r"(a3) : "l"(acc[i][1]));

        float4 o;
        o.x = __uint_as_float(a0) + cb4.x + s0;
        o.y = __uint_as_float(a1) + cb4.y + c0;
        o.z = __uint_as_float(a2) + cb4.z + s1;
        o.w = __uint_as_float(a3) + cb4.w + c1;
        *(float4*)&out[((size_t)b * Pc + p) * Dc + td * 4] = o;
    }
}

extern "C" void kernel_launch(void* const* d_in, const int* in_sizes, int n_in,
                              void* d_out, int out_size) {
    const float* x  = (const float*)d_in[0];   // [B, L, M]
    const float* ts = (const float*)d_in[1];   // [B, L]
    const float* w  = (const float*)d_in[2];   // [D, M, K]
    const float* cb = (const float*)d_in[3];   // [D]
    float* out = (float*)d_out;                // [B, P, D]

    wt_transpose_kernel<<<(RED * Dc + 255) / 256, 256>>>(w);

    dim3 grid((Pc + TILE_P - 1) / TILE_P, Bc); // (128, 32)
    patch_encoder_kernel<<<grid, 256>>>(x, ts, cb, out);
}

// round 5
// speedup vs baseline: 2.6819x; 2.6819x over previous
#include <cuda_runtime.h>
#include <cuda_fp16.h>
#include <cstdint>

#define Bc      32
#define Lc      32768
#define Mc      32
#define Dc      128
#define Pc      4095
#define TILE_P  128
#define NCH     16          // K chunks of 32 (one time-row each)
#define BUFB    32768       // Ah(8K) Al(8K) Bh(8K) Bl(8K)
#define SMEM_TOTAL (2 * BUFB)

// weights pre-split to fp16 hi/lo, layout [d][k*32+m] (K-contiguous, matches x slab)
__device__ __align__(16) __half g_Bh[Dc * 512];
__device__ __align__(16) __half g_Bl[Dc * 512];

__global__ void prep_b(const float* __restrict__ w) {
    int idx = blockIdx.x * 256 + threadIdx.x;
    if (idx >= Dc * 512) return;
    int d = idx >> 9, t = idx & 511;
    int k = t >> 5, m = t & 31;
    float v = w[d * 512 + m * 16 + k];
    __half h = __float2half_rn(v);
    g_Bh[idx] = h;
    g_Bl[idx] = __float2half_rn(v - __half2float(h));
}

#define LDSM4(f, a)                                                           \
    asm volatile("ldmatrix.sync.aligned.m8n8.x4.shared.b16 {%0,%1,%2,%3},[%4];" \
        : "=r"((f)[0]), "=r"((f)[1]), "=r"((f)[2]), "=r"((f)[3]) : "r"(a))

#define MMA(c4, a, b0, b1)                                                    \
    asm volatile("mma.sync.aligned.m16n8k16.row.col.f32.f16.f16.f32 "         \
        "{%0,%1,%2,%3},{%4,%5,%6,%7},{%8,%9},{%0,%1,%2,%3};"                  \
        : "+f"((c4)[0]), "+f"((c4)[1]), "+f"((c4)[2]), "+f"((c4)[3])          \
        : "r"((a)[0]), "r"((a)[1]), "r"((a)[2]), "r"((a)[3]), "r"(b0), "r"(b1))

__device__ __forceinline__ uint32_t h2u(__half2 v) { return *reinterpret_cast<uint32_t*>(&v); }

__global__ __launch_bounds__(512, 1) void patch_encoder_mma(
    const float* __restrict__ x, const float* __restrict__ ts,
    const float* __restrict__ cb, float* __restrict__ out)
{
    extern __shared__ char smc[];
    uint32_t sbase;
    asm("{ .reg .u64 t; cvta.to.shared.u64 t, %1; cvt.u32.u64 %0, t; }"
        : "=r"(sbase) : "l"(smc));

    const int tid  = threadIdx.x;
    const int lane = tid & 31;
    const int wid  = tid >> 5;
    const int wp   = wid >> 1;     // 0..7 : p-tile of 16
    const int wdn  = wid & 1;      // 0..1 : d-tile of 64
    const int b    = blockIdx.y;
    const int p0   = blockIdx.x * TILE_P;

    // ---- staging indices: thread handles row sr (0..127), quarter sq (8 elems) ----
    const int sr = tid >> 2, sq = tid & 3;
    int gpc = p0 + sr; if (gpc > Pc - 1) gpc = Pc - 1;           // clamp (discarded rows)
    const float* xsrc = x + ((size_t)b * Lc + (size_t)gpc * 8) * Mc + sq * 8;
    const char*  bhsrc = (const char*)g_Bh + sr * 1024 + sq * 16;
    const char*  blsrc = (const char*)g_Bl + sr * 1024 + sq * 16;
    const uint32_t sts_off = sr * 64 + ((sq * 16) ^ ((sr * 8) & 0x30));

    float4 av0, av1; uint4 bhv, blv;

    auto LDG = [&](int c) {
        const float4* p = reinterpret_cast<const float4*>(xsrc + (size_t)c * Mc);
        av0 = p[0]; av1 = p[1];
        bhv = *reinterpret_cast<const uint4*>(bhsrc + c * 64);
        blv = *reinterpret_cast<const uint4*>(blsrc + c * 64);
    };
    auto STS = [&](int bi) {
        char* base = smc + bi * BUFB;
        float f[8] = { av0.x, av0.y, av0.z, av0.w, av1.x, av1.y, av1.z, av1.w };
        __half h[8], l[8];
        #pragma unroll
        for (int e = 0; e < 8; ++e) {
            h[e] = __float2half_rn(f[e]);
            l[e] = __float2half_rn(f[e] - __half2float(h[e]));
        }
        uint4 hv, lv;
        hv.x = h2u(__halves2half2(h[0], h[1])); hv.y = h2u(__halves2half2(h[2], h[3]));
        hv.z = h2u(__halves2half2(h[4], h[5])); hv.w = h2u(__halves2half2(h[6], h[7]));
        lv.x = h2u(__halves2half2(l[0], l[1])); lv.y = h2u(__halves2half2(l[2], l[3]));
        lv.z = h2u(__halves2half2(l[4], l[5])); lv.w = h2u(__halves2half2(l[6], l[7]));
        *reinterpret_cast<uint4*>(base +         sts_off) = hv;   // A_hi
        *reinterpret_cast<uint4*>(base +  8192 + sts_off) = lv;   // A_lo
        *reinterpret_cast<uint4*>(base + 16384 + sts_off) = bhv;  // B_hi
        *reinterpret_cast<uint4*>(base + 24576 + sts_off) = blv;  // B_lo
    };

    // ---- ldmatrix per-lane address components ----
    const uint32_t lrow   = lane & 15;
    const uint32_t colsel = (lane >> 4) * 16;       // bytes
    const uint32_t msk    = (lrow * 8) & 0x30;      // swizzle mask (row-dependent)
    const uint32_t aRow   = (wp * 16 + lrow) * 64;
    const uint32_t bRow0  = (wdn * 64 + lrow) * 64;

    float acc[8][4];
    #pragma unroll
    for (int j = 0; j < 8; ++j)
        #pragma unroll
        for (int e = 0; e < 4; ++e) acc[j][e] = 0.f;

    auto MATH = [&](int bi) {
        uint32_t base = sbase + bi * BUFB;
        #pragma unroll
        for (int k = 0; k < 2; ++k) {
            uint32_t coff = (k * 32 + colsel) ^ msk;
            uint32_t ah[4], al[4];
            LDSM4(ah, base + aRow + coff);
            LDSM4(al, base + 8192 + aRow + coff);
            #pragma unroll
            for (int nt = 0; nt < 4; ++nt) {
                uint32_t bh[4], bl[4];
                uint32_t baddr = base + 16384 + bRow0 + nt * 1024 + coff;
                LDSM4(bh, baddr);
                LDSM4(bl, baddr + 8192);
                const int j = nt * 2;
                MMA(acc[j],     ah, bh[0], bh[2]);
                MMA(acc[j],     al, bh[0], bh[2]);
                MMA(acc[j],     ah, bl[0], bl[2]);
                MMA(acc[j + 1], ah, bh[1], bh[3]);
                MMA(acc[j + 1], al, bh[1], bh[3]);
                MMA(acc[j + 1], ah, bl[1], bl[3]);
            }
        }
    };

    // ---- pipelined main loop ----
    LDG(0); STS(0);
    __syncthreads();
    for (int c = 0; c < NCH; ++c) {
        if (c + 1 < NCH) LDG(c + 1);        // prefetch overlaps MMA
        MATH(c & 1);
        __syncthreads();
        if (c + 1 < NCH) {
            STS((c + 1) & 1);
            __syncthreads();
        }
    }

    // ---- epilogue: bias + sinusoidal PE (median == ts[p*8+7]; windows pre-sorted) ----
    const int tq = lane >> 2, tr = lane & 3;
    const int gp1 = p0 + wp * 16 + tq;      // always < Pc
    const int gp2 = gp1 + 8;                // can be Pc-invalid only in last block
    const float med1 = ts[(size_t)b * Lc + gp1 * 8 + 7];
    const float med2 = ts[(size_t)b * Lc + gp2 * 8 + 7];
    const bool  v2   = gp2 < Pc;
    float* o1 = out + ((size_t)b * Pc + gp1) * Dc;
    float* o2 = out + ((size_t)b * Pc + gp2) * Dc;
    const float CC = -0.0719557839f;        // -ln(10000)/128

    #pragma unroll
    for (int j = 0; j < 8; ++j) {
        int c = wdn * 64 + j * 8 + tr * 2;
        float fr = expf((float)c * CC);
        float2 bb = *reinterpret_cast<const float2*>(cb + c);
        float s, co;
        sincosf(med1 * fr, &s, &co);
        float2 r1 = { acc[j][0] + bb.x + s, acc[j][1] + bb.y + co };
        *reinterpret_cast<float2*>(o1 + c) = r1;
        sincosf(med2 * fr, &s, &co);
        if (v2) {
            float2 r2 = { acc[j][2] + bb.x + s, acc[j][3] + bb.y + co };
            *reinterpret_cast<float2*>(o2 + c) = r2;
        }
    }
}

extern "C" void kernel_launch(void* const* d_in, const int* in_sizes, int n_in,
                              void* d_out, int out_size) {
    const float* x  = (const float*)d_in[0];   // [B, L, M]
    const float* ts = (const float*)d_in[1];   // [B, L]
    const float* w  = (const float*)d_in[2];   // [D, M, K]
    const float* cb = (const float*)d_in[3];   // [D]
    float* out = (float*)d_out;                // [B, P, D]

    cudaFuncSetAttribute(patch_encoder_mma,
                         cudaFuncAttributeMaxDynamicSharedMemorySize, SMEM_TOTAL);

    prep_b<<<(Dc * 512 + 255) / 256, 256>>>(w);

    dim3 grid((Pc + TILE_P - 1) / TILE_P, Bc);   // (32, 32)
    patch_encoder_mma<<<grid, 512, SMEM_TOTAL>>>(x, ts, cb, out);
}

// round 6
// speedup vs baseline: 3.5913x; 1.3391x over previous
#include <cuda_runtime.h>
#include <cuda_fp16.h>
#include <cstdint>

#define Bc      32
#define Lc      32768
#define Mc      32
#define Dc      128
#define Pc      4095
#define TILE_P  128
#define NCH     16          // K chunks of 32 (one time-row each)
#define BUFB    16384       // A(8K) + B(8K)
#define SMEM_TOTAL (2 * BUFB)

// weights as fp16, layout [d][k*32+m] (K-contiguous, matches x slab)
__device__ __align__(16) __half g_Bh[Dc * 512];

__global__ void prep_b(const float* __restrict__ w) {
    int idx = blockIdx.x * 256 + threadIdx.x;
    if (idx >= Dc * 512) return;
    int d = idx >> 9, t = idx & 511;
    int k = t >> 5, m = t & 31;
    g_Bh[idx] = __float2half_rn(w[d * 512 + m * 16 + k]);
}

#define LDSM4(f, a)                                                           \
    asm volatile("ldmatrix.sync.aligned.m8n8.x4.shared.b16 {%0,%1,%2,%3},[%4];" \
        : "=r"((f)[0]), "=r"((f)[1]), "=r"((f)[2]), "=r"((f)[3]) : "r"(a))

#define MMA(c4, a, b0, b1)                                                    \
    asm volatile("mma.sync.aligned.m16n8k16.row.col.f32.f16.f16.f32 "         \
        "{%0,%1,%2,%3},{%4,%5,%6,%7},{%8,%9},{%0,%1,%2,%3};"                  \
        : "+f"((c4)[0]), "+f"((c4)[1]), "+f"((c4)[2]), "+f"((c4)[3])          \
        : "r"((a)[0]), "r"((a)[1]), "r"((a)[2]), "r"((a)[3]), "r"(b0), "r"(b1))

__device__ __forceinline__ uint32_t h2u(__half2 v) { return *reinterpret_cast<uint32_t*>(&v); }

__global__ __launch_bounds__(512, 2) void patch_encoder_mma(
    const float* __restrict__ x, const float* __restrict__ ts,
    const float* __restrict__ cb, float* __restrict__ out)
{
    extern __shared__ char smc[];
    uint32_t sbase;
    asm("{ .reg .u64 t; cvta.to.shared.u64 t, %1; cvt.u32.u64 %0, t; }"
        : "=r"(sbase) : "l"(smc));

    const int tid  = threadIdx.x;
    const int lane = tid & 31;
    const int wid  = tid >> 5;
    const int wp   = wid >> 1;     // 0..7 : p-tile of 16
    const int wdn  = wid & 1;      // 0..1 : d-tile of 64
    const int b    = blockIdx.y;
    const int p0   = blockIdx.x * TILE_P;

    // ---- staging indices: thread handles row sr (0..127), quarter sq (8 elems) ----
    const int sr = tid >> 2, sq = tid & 3;
    int gpc = p0 + sr; if (gpc > Pc - 1) gpc = Pc - 1;           // clamp (rows discarded)
    const float* xsrc  = x + ((size_t)b * Lc + (size_t)gpc * 8) * Mc + sq * 8;
    const char*  bhsrc = (const char*)g_Bh + sr * 1024 + sq * 16;
    const uint32_t sts_off = sr * 64 + ((sq * 16) ^ ((sr * 8) & 0x30));

    float4 av0, av1; uint4 bhv;

    auto LDG = [&](int c) {
        const float4* p = reinterpret_cast<const float4*>(xsrc + (size_t)c * Mc);
        av0 = p[0]; av1 = p[1];
        bhv = *reinterpret_cast<const uint4*>(bhsrc + c * 64);
    };
    auto STS = [&](int bi) {
        char* base = smc + bi * BUFB;
        uint4 hv;
        hv.x = h2u(__floats2half2_rn(av0.x, av0.y));
        hv.y = h2u(__floats2half2_rn(av0.z, av0.w));
        hv.z = h2u(__floats2half2_rn(av1.x, av1.y));
        hv.w = h2u(__floats2half2_rn(av1.z, av1.w));
        *reinterpret_cast<uint4*>(base +        sts_off) = hv;    // A (fp16 x)
        *reinterpret_cast<uint4*>(base + 8192 + sts_off) = bhv;   // B (fp16 w)
    };

    // ---- ldmatrix per-lane address components ----
    const uint32_t lrow   = lane & 15;
    const uint32_t colsel = (lane >> 4) * 16;       // bytes
    const uint32_t msk    = (lrow * 8) & 0x30;      // swizzle mask (row-dependent)
    const uint32_t aRow   = (wp * 16 + lrow) * 64;
    const uint32_t bRow0  = (wdn * 64 + lrow) * 64;

    float acc[8][4];
    #pragma unroll
    for (int j = 0; j < 8; ++j)
        #pragma unroll
        for (int e = 0; e < 4; ++e) acc[j][e] = 0.f;

    auto MATH = [&](int bi) {
        uint32_t base = sbase + bi * BUFB;
        #pragma unroll
        for (int k = 0; k < 2; ++k) {
            uint32_t coff = (k * 32 + colsel) ^ msk;
            uint32_t ah[4];
            LDSM4(ah, base + aRow + coff);
            #pragma unroll
            for (int nt = 0; nt < 4; ++nt) {
                uint32_t bh[4];
                LDSM4(bh, base + 8192 + bRow0 + nt * 1024 + coff);
                MMA(acc[nt * 2],     ah, bh[0], bh[2]);
                MMA(acc[nt * 2 + 1], ah, bh[1], bh[3]);
            }
        }
    };

    // ---- pipelined main loop ----
    LDG(0); STS(0);
    __syncthreads();
    for (int c = 0; c < NCH; ++c) {
        if (c + 1 < NCH) LDG(c + 1);        // prefetch overlaps MMA
        MATH(c & 1);
        __syncthreads();
        if (c + 1 < NCH) {
            STS((c + 1) & 1);
            __syncthreads();
        }
    }

    // ---- epilogue: bias + sinusoidal PE (median == ts[p*8+7]; windows pre-sorted) ----
    const int tq = lane >> 2, tr = lane & 3;
    const int gp1 = p0 + wp * 16 + tq;      // always < Pc
    const int gp2 = gp1 + 8;                // can be Pc-invalid only in last block
    const float med1 = ts[(size_t)b * Lc + gp1 * 8 + 7];
    const float med2 = ts[(size_t)b * Lc + gp2 * 8 + 7];
    const bool  v2   = gp2 < Pc;
    float* o1 = out + ((size_t)b * Pc + gp1) * Dc;
    float* o2 = out + ((size_t)b * Pc + gp2) * Dc;
    const float CC = -0.0719557839f;        // -ln(10000)/128

    #pragma unroll
    for (int j = 0; j < 8; ++j) {
        int c = wdn * 64 + j * 8 + tr * 2;
        float fr = expf((float)c * CC);
        float2 bb = *reinterpret_cast<const float2*>(cb + c);
        float s, co;
        sincosf(med1 * fr, &s, &co);
        float2 r1 = { acc[j][0] + bb.x + s, acc[j][1] + bb.y + co };
        *reinterpret_cast<float2*>(o1 + c) = r1;
        sincosf(med2 * fr, &s, &co);
        if (v2) {
            float2 r2 = { acc[j][2] + bb.x + s, acc[j][3] + bb.y + co };
            *reinterpret_cast<float2*>(o2 + c) = r2;
        }
    }
}

extern "C" void kernel_launch(void* const* d_in, const int* in_sizes, int n_in,
                              void* d_out, int out_size) {
    const float* x  = (const float*)d_in[0];   // [B, L, M]
    const float* ts = (const float*)d_in[1];   // [B, L]
    const float* w  = (const float*)d_in[2];   // [D, M, K]
    const float* cb = (const float*)d_in[3];   // [D]
    float* out = (float*)d_out;                // [B, P, D]

    cudaFuncSetAttribute(patch_encoder_mma,
                         cudaFuncAttributeMaxDynamicSharedMemorySize, SMEM_TOTAL);

    prep_b<<<(Dc * 512 + 255) / 256, 256>>>(w);

    dim3 grid((Pc + TILE_P - 1) / TILE_P, Bc);   // (32, 32)
    patch_encoder_mma<<<grid, 512, SMEM_TOTAL>>>(x, ts, cb, out);
}

// round 7
// speedup vs baseline: 4.1182x; 1.1467x over previous
#include <cuda_runtime.h>
#include <cuda_fp16.h>
#include <cstdint>

#define Bc      32
#define Lc      32768
#define Mc      32
#define Dc      128
#define Pc      4095
#define TILE_P  128
#define NCH     16          // K chunks of 32 (one time-row each)
#define BUFB    16384       // A(8K) + B(8K)
#define SMEM_TOTAL (2 * BUFB)

// weights as fp16, layout [d][k*32+m] (K-contiguous, matches x slab)
__device__ __align__(16) __half g_Bh[Dc * 512];

__global__ void prep_b(const float* __restrict__ w) {
    int idx = blockIdx.x * 256 + threadIdx.x;
    if (idx >= Dc * 512) return;
    int d = idx >> 9, t = idx & 511;
    int k = t >> 5, m = t & 31;
    g_Bh[idx] = __float2half_rn(w[d * 512 + m * 16 + k]);
}

#define LDSM4(f, a)                                                           \
    asm volatile("ldmatrix.sync.aligned.m8n8.x4.shared.b16 {%0,%1,%2,%3},[%4];" \
        : "=r"((f)[0]), "=r"((f)[1]), "=r"((f)[2]), "=r"((f)[3]) : "r"(a))

#define MMA(c4, a, b0, b1)                                                    \
    asm volatile("mma.sync.aligned.m16n8k16.row.col.f32.f16.f16.f32 "         \
        "{%0,%1,%2,%3},{%4,%5,%6,%7},{%8,%9},{%0,%1,%2,%3};"                  \
        : "+f"((c4)[0]), "+f"((c4)[1]), "+f"((c4)[2]), "+f"((c4)[3])          \
        : "r"((a)[0]), "r"((a)[1]), "r"((a)[2]), "r"((a)[3]), "r"(b0), "r"(b1))

#define CP_ASYNC16(dst, src)                                                  \
    asm volatile("cp.async.cg.shared.global [%0], [%1], 16;" :: "r"(dst), "l"(src))
#define CP_COMMIT()  asm volatile("cp.async.commit_group;" ::: "memory")
#define CP_WAIT0()   asm volatile("cp.async.wait_group 0;" ::: "memory")

__device__ __forceinline__ uint32_t h2u(__half2 v) { return *reinterpret_cast<uint32_t*>(&v); }

__global__ __launch_bounds__(256, 2) void patch_encoder_mma(
    const float* __restrict__ x, const float* __restrict__ ts,
    const float* __restrict__ cb, float* __restrict__ out)
{
    extern __shared__ char smc[];
    uint32_t sbase;
    asm("{ .reg .u64 t; cvta.to.shared.u64 t, %1; cvt.u32.u64 %0, t; }"
        : "=r"(sbase) : "l"(smc));

    const int tid  = threadIdx.x;
    const int lane = tid & 31;
    const int wid  = tid >> 5;
    const int wp   = wid >> 1;     // 0..3 : p-tile of 32
    const int wdn  = wid & 1;      // 0..1 : d-tile of 64
    const int b    = blockIdx.y;
    const int p0   = blockIdx.x * TILE_P;

    // ---- staging indices: thread handles row sr (0..127), half sq (16 elems) ----
    const int sr = tid >> 1, sq = tid & 1;
    int gpc = p0 + sr; if (gpc > Pc - 1) gpc = Pc - 1;           // clamp (rows discarded)
    const float* xsrc = x + ((size_t)b * Lc + (size_t)gpc * 8) * Mc + sq * 16;
    // swizzled smem offsets for this thread's two 16B units (row sr, 64B rows)
    const uint32_t so0 = sr * 64 + ((sq * 32)      ^ ((sr * 8) & 0x30));
    const uint32_t so1 = sr * 64 + ((sq * 32 + 16) ^ ((sr * 8) & 0x30));
    const char* bsrc = (const char*)g_Bh + sr * 1024 + sq * 32;  // + c*64 per chunk

    float4 av0, av1, av2, av3;

    auto LDGx = [&](int c) {
        const float4* p = reinterpret_cast<const float4*>(xsrc + (size_t)c * Mc);
        av0 = p[0]; av1 = p[1]; av2 = p[2]; av3 = p[3];
    };
    auto STSa = [&](int bi) {
        char* base = smc + bi * BUFB;
        uint4 h0, h1;
        h0.x = h2u(__floats2half2_rn(av0.x, av0.y));
        h0.y = h2u(__floats2half2_rn(av0.z, av0.w));
        h0.z = h2u(__floats2half2_rn(av1.x, av1.y));
        h0.w = h2u(__floats2half2_rn(av1.z, av1.w));
        h1.x = h2u(__floats2half2_rn(av2.x, av2.y));
        h1.y = h2u(__floats2half2_rn(av2.z, av2.w));
        h1.z = h2u(__floats2half2_rn(av3.x, av3.y));
        h1.w = h2u(__floats2half2_rn(av3.z, av3.w));
        *reinterpret_cast<uint4*>(base + so0) = h0;
        *reinterpret_cast<uint4*>(base + so1) = h1;
    };
    auto CPb = [&](int c, int bi) {
        uint32_t dst = sbase + bi * BUFB + 8192;
        const char* s = bsrc + c * 64;
        CP_ASYNC16(dst + so0, s);
        CP_ASYNC16(dst + so1, s + 16);
        CP_COMMIT();
    };

    // ---- ldmatrix per-lane address components ----
    const uint32_t lrow   = lane & 15;
    const uint32_t colsel = (lane >> 4) * 16;       // bytes
    const uint32_t msk    = (lrow * 8) & 0x30;      // swizzle mask (row-dependent)
    const uint32_t aRow0  = (wp * 32 + lrow) * 64;  // m-tile 0 (+16*64 for m-tile 1)
    const uint32_t bRow0  = (wdn * 64 + lrow) * 64;

    float acc[2][8][4];
    #pragma unroll
    for (int mt = 0; mt < 2; ++mt)
        #pragma unroll
        for (int j = 0; j < 8; ++j)
            #pragma unroll
            for (int e = 0; e < 4; ++e) acc[mt][j][e] = 0.f;

    auto MATH = [&](int bi) {
        uint32_t base = sbase + bi * BUFB;
        #pragma unroll
        for (int k = 0; k < 2; ++k) {
            uint32_t coff = (k * 32 + colsel) ^ msk;
            uint32_t ah[2][4];
            LDSM4(ah[0], base + aRow0 + coff);
            LDSM4(ah[1], base + aRow0 + 1024 + coff);    // +16 rows
            #pragma unroll
            for (int nt = 0; nt < 4; ++nt) {
                uint32_t bh[4];
                LDSM4(bh, base + 8192 + bRow0 + nt * 1024 + coff);
                #pragma unroll
                for (int mt = 0; mt < 2; ++mt) {
                    MMA(acc[mt][nt * 2],     ah[mt], bh[0], bh[2]);
                    MMA(acc[mt][nt * 2 + 1], ah[mt], bh[1], bh[3]);
                }
            }
        }
    };

    // ---- pipelined main loop ----
    CPb(0, 0); LDGx(0); STSa(0);
    CP_WAIT0();
    __syncthreads();
    for (int c = 0; c < NCH; ++c) {
        if (c + 1 < NCH) { CPb(c + 1, (c + 1) & 1); LDGx(c + 1); }
        MATH(c & 1);
        __syncthreads();
        if (c + 1 < NCH) {
            STSa((c + 1) & 1);
            CP_WAIT0();
            __syncthreads();
        }
    }

    // ---- epilogue: bias + sinusoidal PE (median == ts[p*8+7]; windows pre-sorted) ----
    const int tq = lane >> 2, tr = lane & 3;
    const float CC = -0.0719557839f;        // -ln(10000)/128

    #pragma unroll
    for (int mt = 0; mt < 2; ++mt) {
        const int gp1 = p0 + wp * 32 + mt * 16 + tq;
        const int gp2 = gp1 + 8;
        // ts index for p=4095 is 32767 (in bounds) even though that row is discarded
        const float med1 = ts[(size_t)b * Lc + gp1 * 8 + 7];
        const float med2 = ts[(size_t)b * Lc + gp2 * 8 + 7];
        const bool v1 = gp1 < Pc, v2 = gp2 < Pc;
        float* o1 = out + ((size_t)b * Pc + gp1) * Dc;
        float* o2 = out + ((size_t)b * Pc + gp2) * Dc;
        #pragma unroll
        for (int j = 0; j < 8; ++j) {
            int c = wdn * 64 + j * 8 + tr * 2;
            float fr = expf((float)c * CC);
            float2 bb = *reinterpret_cast<const float2*>(cb + c);
            float s, co;
            sincosf(med1 * fr, &s, &co);
            if (v1) {
                float2 r1 = { acc[mt][j][0] + bb.x + s, acc[mt][j][1] + bb.y + co };
                *reinterpret_cast<float2*>(o1 + c) = r1;
            }
            sincosf(med2 * fr, &s, &co);
            if (v2) {
                float2 r2 = { acc[mt][j][2] + bb.x + s, acc[mt][j][3] + bb.y + co };
                *reinterpret_cast<float2*>(o2 + c) = r2;
            }
        }
    }
}

extern "C" void kernel_launch(void* const* d_in, const int* in_sizes, int n_in,
                              void* d_out, int out_size) {
    const float* x  = (const float*)d_in[0];   // [B, L, M]
    const float* ts = (const float*)d_in[1];   // [B, L]
    const float* w  = (const float*)d_in[2];   // [D, M, K]
    const float* cb = (const float*)d_in[3];   // [D]
    float* out = (float*)d_out;                // [B, P, D]

    cudaFuncSetAttribute(patch_encoder_mma,
                         cudaFuncAttributeMaxDynamicSharedMemorySize, SMEM_TOTAL);

    prep_b<<<(Dc * 512 + 255) / 256, 256>>>(w);

    dim3 grid((Pc + TILE_P - 1) / TILE_P, Bc);   // (32, 32)
    patch_encoder_mma<<<grid, 256, SMEM_TOTAL>>>(x, ts, cb, out);
}

// round 9
// speedup vs baseline: 4.6629x; 1.1323x over previous
#include <cuda_runtime.h>
#include <cuda_fp16.h>
#include <cstdint>

#define Bc      32
#define Lc      32768
#define Mc      32
#define Dc      128
#define Pc      4095
#define TILE_P  128
#define NCH     16          // K chunks of 32 (one time-row each)
#define BUFB    16384       // A(8K) + B(8K)
#define SMEM_TOTAL (2 * BUFB)

// weights as fp16, layout [d][k*32+m] (K-contiguous, matches x slab)
__device__ __align__(16) __half g_Bh[Dc * 512];

__global__ void prep_b(const float* __restrict__ w) {
    int idx = blockIdx.x * 256 + threadIdx.x;
    if (idx >= Dc * 512) return;
    int d = idx >> 9, t = idx & 511;
    int k = t >> 5, m = t & 31;
    g_Bh[idx] = __float2half_rn(w[d * 512 + m * 16 + k]);
}

#define LDSM4(f, a)                                                           \
    asm volatile("ldmatrix.sync.aligned.m8n8.x4.shared.b16 {%0,%1,%2,%3},[%4];" \
        : "=r"((f)[0]), "=r"((f)[1]), "=r"((f)[2]), "=r"((f)[3]) : "r"(a))

#define MMA(c4, a, b0, b1)                                                    \
    asm volatile("mma.sync.aligned.m16n8k16.row.col.f32.f16.f16.f32 "         \
        "{%0,%1,%2,%3},{%4,%5,%6,%7},{%8,%9},{%0,%1,%2,%3};"                  \
        : "+f"((c4)[0]), "+f"((c4)[1]), "+f"((c4)[2]), "+f"((c4)[3])          \
        : "r"((a)[0]), "r"((a)[1]), "r"((a)[2]), "r"((a)[3]), "r"(b0), "r"(b1))

#define CP_ASYNC16(dst, src)                                                  \
    asm volatile("cp.async.cg.shared.global [%0], [%1], 16;" :: "r"(dst), "l"(src))
#define CP_COMMIT()  asm volatile("cp.async.commit_group;" ::: "memory")
#define CP_WAIT0()   asm volatile("cp.async.wait_group 0;" ::: "memory")

__device__ __forceinline__ uint32_t h2u(__half2 v) { return *reinterpret_cast<uint32_t*>(&v); }

__global__ __launch_bounds__(256, 2) void patch_encoder_mma(
    const float* __restrict__ x, const float* __restrict__ ts,
    const float* __restrict__ cb, float* __restrict__ out)
{
    extern __shared__ char smc[];
    uint32_t sbase;
    asm("{ .reg .u64 t; cvta.to.shared.u64 t, %1; cvt.u32.u64 %0, t; }"
        : "=r"(sbase) : "l"(smc));

    const int tid  = threadIdx.x;
    const int lane = tid & 31;
    const int wid  = tid >> 5;
    const int wp   = wid >> 1;     // 0..3 : p-tile of 32
    const int wdn  = wid & 1;      // 0..1 : d-tile of 64
    const int b    = blockIdx.y;
    const int p0   = blockIdx.x * TILE_P;

    // ---- staging indices: thread handles row sr (0..127), half sq (16 elems) ----
    const int sr = tid >> 1, sq = tid & 1;
    int gpc = p0 + sr; if (gpc > Pc - 1) gpc = Pc - 1;           // clamp (rows discarded)
    const float* xsrc = x + ((size_t)b * Lc + (size_t)gpc * 8) * Mc + sq * 16;
    // swizzled smem offsets for this thread's two 16B units (row sr, 64B rows)
    const uint32_t so0 = sr * 64 + ((sq * 32)      ^ ((sr * 8) & 0x30));
    const uint32_t so1 = sr * 64 + ((sq * 32 + 16) ^ ((sr * 8) & 0x30));
    const char* bsrc = (const char*)g_Bh + sr * 1024 + sq * 32;  // + c*64 per chunk

    float4 av0, av1, av2, av3;

    auto LDGx = [&](int c) {
        const float4* p = reinterpret_cast<const float4*>(xsrc + (size_t)c * Mc);
        av0 = p[0]; av1 = p[1]; av2 = p[2]; av3 = p[3];
    };
    auto STSa = [&](int bi) {
        char* base = smc + bi * BUFB;
        uint4 h0, h1;
        h0.x = h2u(__floats2half2_rn(av0.x, av0.y));
        h0.y = h2u(__floats2half2_rn(av0.z, av0.w));
        h0.z = h2u(__floats2half2_rn(av1.x, av1.y));
        h0.w = h2u(__floats2half2_rn(av1.z, av1.w));
        h1.x = h2u(__floats2half2_rn(av2.x, av2.y));
        h1.y = h2u(__floats2half2_rn(av2.z, av2.w));
        h1.z = h2u(__floats2half2_rn(av3.x, av3.y));
        h1.w = h2u(__floats2half2_rn(av3.z, av3.w));
        *reinterpret_cast<uint4*>(base + so0) = h0;
        *reinterpret_cast<uint4*>(base + so1) = h1;
    };
    auto CPb = [&](int c, int bi) {
        uint32_t dst = sbase + bi * BUFB + 8192;
        const char* s = bsrc + c * 64;
        CP_ASYNC16(dst + so0, s);
        CP_ASYNC16(dst + so1, s + 16);
        CP_COMMIT();
    };

    // ---- ldmatrix per-lane address components ----
    const uint32_t lrow   = lane & 15;
    const uint32_t colsel = (lane >> 4) * 16;       // bytes
    const uint32_t msk    = (lrow * 8) & 0x30;      // swizzle mask (row-dependent)
    const uint32_t aRow0  = (wp * 32 + lrow) * 64;  // m-tile 0 (+16*64 for m-tile 1)
    const uint32_t bRow0  = (wdn * 64 + lrow) * 64;

    float acc[2][8][4];
    #pragma unroll
    for (int mt = 0; mt < 2; ++mt)
        #pragma unroll
        for (int j = 0; j < 8; ++j)
            #pragma unroll
            for (int e = 0; e < 4; ++e) acc[mt][j][e] = 0.f;

    auto MATH = [&](int bi) {
        uint32_t base = sbase + bi * BUFB;
        #pragma unroll
        for (int k = 0; k < 2; ++k) {
            uint32_t coff = (k * 32 + colsel) ^ msk;
            uint32_t ah[2][4];
            LDSM4(ah[0], base + aRow0 + coff);
            LDSM4(ah[1], base + aRow0 + 1024 + coff);    // +16 rows
            #pragma unroll
            for (int nt = 0; nt < 4; ++nt) {
                uint32_t bh[4];
                LDSM4(bh, base + 8192 + bRow0 + nt * 1024 + coff);
                #pragma unroll
                for (int mt = 0; mt < 2; ++mt) {
                    MMA(acc[mt][nt * 2],     ah[mt], bh[0], bh[2]);
                    MMA(acc[mt][nt * 2 + 1], ah[mt], bh[1], bh[3]);
                }
            }
        }
    };

    // ---- pipelined main loop: ONE barrier per chunk ----
    // iter c:  STSa(c) ; wait B(c) [issued in iter c-1, overlapped] ; barrier ;
    //          issue LDG/CPb(c+1) ; MATH(c)
    // Hazards: STSa(c) overwrites A-buf read by MATH(c-2)  (pre iter c-1 barrier) OK
    //          CPb(c+1) overwrites B-buf read by MATH(c-1) (pre iter c   barrier) OK
    LDGx(0); CPb(0, 0);
    #pragma unroll 4
    for (int c = 0; c < NCH; ++c) {
        STSa(c & 1);
        CP_WAIT0();
        __syncthreads();
        if (c + 1 < NCH) {
            LDGx(c + 1);
            CPb(c + 1, (c + 1) & 1);
        }
        MATH(c & 1);
    }

    // ---- epilogue: bias + sinusoidal PE (median == ts[p*8+7]; windows pre-sorted) ----
    const int tq = lane >> 2, tr = lane & 3;
    const float CC = -0.0719557839f;        // -ln(10000)/128

    // frequencies + bias are mt-invariant: compute once
    float fr[8]; float2 bb[8];
    #pragma unroll
    for (int j = 0; j < 8; ++j) {
        int c = wdn * 64 + j * 8 + tr * 2;
        fr[j] = expf((float)c * CC);
        bb[j] = *reinterpret_cast<const float2*>(cb + c);
    }

    #pragma unroll
    for (int mt = 0; mt < 2; ++mt) {
        const int gp1 = p0 + wp * 32 + mt * 16 + tq;
        const int gp2 = gp1 + 8;
        const float med1 = ts[(size_t)b * Lc + gp1 * 8 + 7];
        const float med2 = ts[(size_t)b * Lc + gp2 * 8 + 7];
        const bool v1 = gp1 < Pc, v2 = gp2 < Pc;
        float* o1 = out + ((size_t)b * Pc + gp1) * Dc;
        float* o2 = out + ((size_t)b * Pc + gp2) * Dc;
        #pragma unroll
        for (int j = 0; j < 8; ++j) {
            int c = wdn * 64 + j * 8 + tr * 2;
            float s, co;
            sincosf(med1 * fr[j], &s, &co);
            if (v1) {
                float2 r1 = { acc[mt][j][0] + bb[j].x + s, acc[mt][j][1] + bb[j].y + co };
                *reinterpret_cast<float2*>(o1 + c) = r1;
            }
            sincosf(med2 * fr[j], &s, &co);
            if (v2) {
                float2 r2 = { acc[mt][j][2] + bb[j].x + s, acc[mt][j][3] + bb[j].y + co };
                *reinterpret_cast<float2*>(o2 + c) = r2;
            }
        }
    }
}

extern "C" void kernel_launch(void* const* d_in, const int* in_sizes, int n_in,
                              void* d_out, int out_size) {
    const float* x  = (const float*)d_in[0];   // [B, L, M]
    const float* ts = (const float*)d_in[1];   // [B, L]
    const float* w  = (const float*)d_in[2];   // [D, M, K]
    const float* cb = (const float*)d_in[3];   // [D]
    float* out = (float*)d_out;                // [B, P, D]

    cudaFuncSetAttribute(patch_encoder_mma,
                         cudaFuncAttributeMaxDynamicSharedMemorySize, SMEM_TOTAL);

    prep_b<<<(Dc * 512 + 255) / 256, 256>>>(w);

    dim3 grid((Pc + TILE_P - 1) / TILE_P, Bc);   // (32, 32)
    patch_encoder_mma<<<grid, 256, SMEM_TOTAL>>>(x, ts, cb, out);
}